// round 17
// baseline (speedup 1.0000x reference)
#include <cuda_runtime.h>

typedef unsigned long long u64;

#define TPB 128
#define PXT 4                    // pixels per thread (2 f32x2 pairs)
#define PXB (TPB * PXT)          // 512 pixels per block

// constant layout (u64 duplicated pairs):
// [0..95]    W0 (8 rows x 12, z-scale folded, col 11 = 0 pad)
// [96..103]  b0
// [104..167] Wm * 1      (layer 0)
// [168..231] Wm * 0.5    (layer 1)
// [232..295] Wm * 0.25   (layer 2)
// [296..303] bm
// [304..327] Wo / 16     (1/8 residual unscale + 0.5 sigmoid arg)
// [328..330] bo / 2
// [331]      fidpack (24 x 2 bits)
// [332..355] cScale per (l,j): 2^l, or 2^l/sqrt(2pi) for gaus units
#define NCONST 356
__constant__ __align__(16) u64 cW[NCONST];
__device__ u64 g_prep[NCONST];

__device__ __forceinline__ u64 pk2(float lo, float hi) {
    u64 r; asm("mov.b64 %0, {%1, %2};" : "=l"(r) : "f"(lo), "f"(hi)); return r;
}
__device__ __forceinline__ void unpk(u64 v, float& lo, float& hi) {
    asm("mov.b64 {%0, %1}, %2;" : "=f"(lo), "=f"(hi) : "l"(v));
}
__device__ __forceinline__ u64 ffma2(u64 a, u64 b, u64 c) {
    u64 d; asm("fma.rn.f32x2 %0, %1, %2, %3;" : "=l"(d) : "l"(a), "l"(b), "l"(c)); return d;
}
__device__ __forceinline__ u64 fmul2(u64 a, u64 b) {
    u64 d; asm("mul.rn.f32x2 %0, %1, %2;" : "=l"(d) : "l"(a), "l"(b)); return d;
}
__device__ __forceinline__ float sin_ap(float x){ float r; asm("sin.approx.f32 %0, %1;" : "=f"(r) : "f"(x)); return r; }
__device__ __forceinline__ float ex2_ap(float x){ float r; asm("ex2.approx.f32 %0, %1;" : "=f"(r) : "f"(x)); return r; }
__device__ __forceinline__ float tanh_ap(float x){ float r; asm("tanh.approx.f32 %0, %1;" : "=f"(r) : "f"(x)); return r; }

// ---- prep kernel: duplicated weight pairs (with folded scales) + fid pack ----
__global__ void prep_kernel(
    const float* __restrict__ W0, const float* __restrict__ b0,
    const float* __restrict__ Wm, const float* __restrict__ bm,
    const float* __restrict__ Wo, const float* __restrict__ bo,
    const int* __restrict__ masks_raw)
{
    for (int idx = threadIdx.x; idx < 331; idx += TPB) {
        float w;
        if (idx < 96) {
            int j = idx / 12, k = idx % 12;
            w = (k < 11) ? W0[j*11 + k] * (k < 8 ? 0.1f : 1.0f) : 0.0f; // fold z/Z_SCALE; pad
        } else if (idx < 104) w = b0[idx-96];
        else if (idx < 168)   w = Wm[idx-104];           // layer 0: x1
        else if (idx < 232)   w = Wm[idx-168] * 0.5f;    // layer 1: x0.5
        else if (idx < 296)   w = Wm[idx-232] * 0.25f;   // layer 2: x0.25
        else if (idx < 304)   w = bm[idx-296];
        else if (idx < 328)   w = Wo[idx-304] * 0.0625f; // 1/8 unscale * 0.5 sig-arg
        else                  w = bo[idx-328] * 0.5f;
        g_prep[idx] = pk2(w, w);
    }
    if (threadIdx.x == 0) {
        // Parse masks: dtype may be int32 (JAX x64 off) or int64. Detect via
        // "layer 0's 8 entries must be a permutation of 0..7".
        int v[24];
        bool ok32 = true;
        unsigned m = 0;
        #pragma unroll
        for (int i = 0; i < 24; i++) v[i] = masks_raw[i];
        #pragma unroll
        for (int i = 0; i < 8; i++) {
            if ((unsigned)v[i] > 7u) ok32 = false; else m |= 1u << v[i];
        }
        if (!ok32 || m != 0xFFu) {
            const long long* m64 = (const long long*)masks_raw;
            #pragma unroll
            for (int i = 0; i < 24; i++) v[i] = (int)m64[i];
        }
        int fid[24];
        #pragma unroll
        for (int l = 0; l < 3; l++)
            #pragma unroll
            for (int f = 0; f < 4; f++)
                #pragma unroll
                for (int i = 0; i < 2; i++)
                    fid[l*8 + v[l*8 + f*2 + i]] = f;
        u64 pack = 0ull;
        #pragma unroll
        for (int i = 0; i < 24; i++) pack |= ((u64)fid[i]) << (2*i);
        g_prep[331] = pack;
        // cScale per (l,j): 2^l (sin/tanh/id) or 2^l * 1/sqrt(2pi) (gaus)
        #pragma unroll
        for (int l = 0; l < 3; l++) {
            float sclf = (l == 0) ? 1.0f : (l == 1 ? 2.0f : 4.0f);
            #pragma unroll
            for (int j = 0; j < 8; j++) {
                float s = sclf * (fid[l*8 + j] == 1 ? 0.3989422804014327f : 1.0f);
                g_prep[332 + l*8 + j] = pk2(s, s);
            }
        }
    }
}

__global__ __launch_bounds__(TPB, 7) void cppn_kernel(
    const float* __restrict__ x, const float* __restrict__ y, const float* __restrict__ rr,
    const float* __restrict__ z,
    float* __restrict__ outp, long long n)
{
    const int tid = threadIdx.x;

    const u64 fidPack = cW[331];

    const unsigned p32 = (unsigned)blockIdx.x * PXB + (unsigned)tid * PXT;
    const bool ok = ((long long)p32 + PXT <= n);

    // v[q] holds 2^l * out_l for pair q (pixels p+2q, p+2q+1)
    u64 v[2][8];

    // ---- W0 stage, k-chunked: each W0 weight LDCU'd once, used by both pairs ----
    {
        #pragma unroll
        for (int j = 0; j < 8; j++) { v[0][j] = cW[96 + j]; v[1][j] = v[0][j]; }

        const float4* zp = (const float4*)(z + (size_t)p32 * 8);

        { // chunk A: k = 0..3
            u64 ia[2][4];
            if (ok) {
                float4 c0 = zp[0], c1 = zp[2], c2 = zp[4], c3 = zp[6];
                ia[0][0] = pk2(c0.x, c1.x); ia[0][1] = pk2(c0.y, c1.y);
                ia[0][2] = pk2(c0.z, c1.z); ia[0][3] = pk2(c0.w, c1.w);
                ia[1][0] = pk2(c2.x, c3.x); ia[1][1] = pk2(c2.y, c3.y);
                ia[1][2] = pk2(c2.z, c3.z); ia[1][3] = pk2(c2.w, c3.w);
            } else {
                #pragma unroll
                for (int q = 0; q < 2; q++)
                    #pragma unroll
                    for (int k = 0; k < 4; k++) ia[q][k] = 0ull;
            }
            #pragma unroll
            for (int j = 0; j < 8; j++)
                #pragma unroll
                for (int k = 0; k < 4; k++) {
                    u64 w = cW[j*12 + k];
                    v[0][j] = ffma2(ia[0][k], w, v[0][j]);
                    v[1][j] = ffma2(ia[1][k], w, v[1][j]);
                }
        }
        { // chunk B: k = 4..7
            u64 ib[2][4];
            if (ok) {
                float4 c0 = zp[1], c1 = zp[3], c2 = zp[5], c3 = zp[7];
                ib[0][0] = pk2(c0.x, c1.x); ib[0][1] = pk2(c0.y, c1.y);
                ib[0][2] = pk2(c0.z, c1.z); ib[0][3] = pk2(c0.w, c1.w);
                ib[1][0] = pk2(c2.x, c3.x); ib[1][1] = pk2(c2.y, c3.y);
                ib[1][2] = pk2(c2.z, c3.z); ib[1][3] = pk2(c2.w, c3.w);
            } else {
                #pragma unroll
                for (int q = 0; q < 2; q++)
                    #pragma unroll
                    for (int k = 0; k < 4; k++) ib[q][k] = 0ull;
            }
            #pragma unroll
            for (int j = 0; j < 8; j++)
                #pragma unroll
                for (int k = 0; k < 4; k++) {
                    u64 w = cW[j*12 + 4 + k];
                    v[0][j] = ffma2(ib[0][k], w, v[0][j]);
                    v[1][j] = ffma2(ib[1][k], w, v[1][j]);
                }
        }
        { // chunk C: k = 8..10 (x, y, r)
            u64 ic[2][3];
            if (ok) {
                float4 xv = *(const float4*)(x  + p32);
                float4 yv = *(const float4*)(y  + p32);
                float4 rv = *(const float4*)(rr + p32);
                ic[0][0] = pk2(xv.x, xv.y); ic[1][0] = pk2(xv.z, xv.w);
                ic[0][1] = pk2(yv.x, yv.y); ic[1][1] = pk2(yv.z, yv.w);
                ic[0][2] = pk2(rv.x, rv.y); ic[1][2] = pk2(rv.z, rv.w);
            } else {
                #pragma unroll
                for (int q = 0; q < 2; q++)
                    #pragma unroll
                    for (int k = 0; k < 3; k++) ic[q][k] = 0ull;
            }
            #pragma unroll
            for (int j = 0; j < 8; j++)
                #pragma unroll
                for (int k = 0; k < 3; k++) {
                    u64 w = cW[j*12 + 8 + k];
                    v[0][j] = ffma2(ic[0][k], w, v[0][j]);
                    v[1][j] = ffma2(ic[1][k], w, v[1][j]);
                }
        }
    }

    // ---- 3 residual layers; two-pass activation (issue MUFUs early, consume late) ----
    #pragma unroll
    for (int l = 0; l < 3; l++) {
        const int wbase = 104 + l * 64;
        const u64 cgau = pk2(-0.72134752044448f, -0.72134752044448f); // -0.5*log2(e)

        u64 pre[2][8];
        #pragma unroll
        for (int j = 0; j < 8; j++) {
            u64 a0 = cW[296 + j], a1 = a0;
            #pragma unroll
            for (int k = 0; k < 8; k++) {
                u64 w = cW[wbase + j*8 + k];
                a0 = ffma2(v[0][k], w, a0);
                a1 = ffma2(v[1][k], w, a1);
            }
            pre[0][j] = a0; pre[1][j] = a1;
        }
        // pass 1: overwrite pre with UNSCALED activation values (MUFU issue phase)
        #pragma unroll
        for (int j = 0; j < 8; j++) {
            int fid = (int)((fidPack >> (2 * (l*8 + j))) & 3ull);
            if (fid == 0) {
                #pragma unroll
                for (int q = 0; q < 2; q++) {
                    float ta, tb; unpk(pre[q][j], ta, tb);
                    pre[q][j] = pk2(sin_ap(ta), sin_ap(tb));
                }
            } else if (fid == 1) {
                #pragma unroll
                for (int q = 0; q < 2; q++) {
                    u64 t = pre[q][j];
                    u64 arg = fmul2(fmul2(t, t), cgau);
                    float g0, g1; unpk(arg, g0, g1);
                    pre[q][j] = pk2(ex2_ap(g0), ex2_ap(g1));
                }
            } else if (fid == 2) {
                #pragma unroll
                for (int q = 0; q < 2; q++) {
                    float ta, tb; unpk(pre[q][j], ta, tb);
                    pre[q][j] = pk2(tanh_ap(ta), tanh_ap(tb));
                }
            }
            // fid == 3 (id): pre already holds t
        }
        // pass 2: branch-free scaled residual accumulate (MUFU consume phase)
        #pragma unroll
        for (int j = 0; j < 8; j++) {
            u64 sc = cW[332 + l*8 + j];
            v[0][j] = ffma2(pre[0][j], sc, v[0][j]);
            v[1][j] = ffma2(pre[1][j], sc, v[1][j]);
        }
    }

    // ---- output linear (Wo/16, bo/2 prefolded) + sigmoid via tanh ----
    if (ok) {
        float res[12];
        float ua[6];
        #pragma unroll
        for (int o = 0; o < 3; o++) {
            u64 a0 = cW[328 + o], a1 = a0;
            #pragma unroll
            for (int k = 0; k < 8; k++) {
                u64 w = cW[304 + o*8 + k];
                a0 = ffma2(v[0][k], w, a0);
                a1 = ffma2(v[1][k], w, a1);
            }
            unpk(a0, ua[o*2], ua[o*2+1]);       // pixels p, p+1 for channel o? no:
        }
        // ua layout: [o*2] = pair0 lo (px p), [o*2+1] = pair0 hi (px p+1)
        // second pair handled below; recompute for clarity to keep regs low
        #pragma unroll
        for (int o = 0; o < 3; o++) {
            res[o]     = fmaf(tanh_ap(ua[o*2]),   0.5f, 0.5f);
            res[3 + o] = fmaf(tanh_ap(ua[o*2+1]), 0.5f, 0.5f);
        }
        #pragma unroll
        for (int o = 0; o < 3; o++) {
            u64 a1 = cW[328 + o];
            #pragma unroll
            for (int k = 0; k < 8; k++) a1 = ffma2(v[1][k], cW[304 + o*8 + k], a1);
            float u2, u3; unpk(a1, u2, u3);
            res[6 + o] = fmaf(tanh_ap(u2), 0.5f, 0.5f);
            res[9 + o] = fmaf(tanh_ap(u3), 0.5f, 0.5f);
        }
        float4* op = (float4*)(outp + (size_t)p32 * 3);   // p % 4 == 0 -> 16B aligned
        op[0] = make_float4(res[0], res[1], res[2],  res[3]);
        op[1] = make_float4(res[4], res[5], res[6],  res[7]);
        op[2] = make_float4(res[8], res[9], res[10], res[11]);
    }
}

extern "C" void kernel_launch(void* const* d_in, const int* in_sizes, int n_in,
                              void* d_out, int out_size) {
    const float* x  = (const float*)d_in[0];
    const float* y  = (const float*)d_in[1];
    const float* r  = (const float*)d_in[2];
    const float* z  = (const float*)d_in[3];
    const float* W0 = (const float*)d_in[4];
    const float* b0 = (const float*)d_in[5];
    const float* Wm = (const float*)d_in[6];
    const float* bm = (const float*)d_in[7];
    const float* Wo = (const float*)d_in[8];
    const float* bo = (const float*)d_in[9];
    const int* masks = (const int*)d_in[10];

    long long n = (long long)in_sizes[0];

    prep_kernel<<<1, TPB>>>(W0, b0, Wm, bm, Wo, bo, masks);

    // Resolve the REAL device address of g_prep (symbol name in host code is
    // only a shadow) and copy into the constant bank as a graph memcpy node.
    void* src = 0;
    cudaGetSymbolAddress(&src, g_prep);
    cudaMemcpyToSymbolAsync(cW, src, NCONST * sizeof(u64), 0,
                            cudaMemcpyDeviceToDevice, 0);

    int blocks = (int)((n + PXB - 1) / PXB);
    cppn_kernel<<<blocks, TPB>>>(x, y, r, z, (float*)d_out, n);
}